// round 4
// baseline (speedup 1.0000x reference)
#include <cuda_runtime.h>
#include <cstdint>

// Quantizer: per-row symmetric int4 quant + nibble pack.
// (Resubmission of Round-2 kernel — previous round was an infra failure,
//  "GB300 container failed twice"; no signal on this source yet.)
//
// x: [N=8192, H=4096] fp32
//
// Harness output is the CONCATENATION of (packed, scales) upcast to float32:
//   out[0 .. N*H/2)          fp32  value of each packed signed byte
//                                  (low nibble = even col, high nibble = odd col)
//   out[N*H/2 .. N*H/2 + N)  fp32  per-row scales (absmax / 7)

#define H 4096
#define HP (H / 2)          // 2048 packed bytes (as floats) per row
#define THREADS 256
// Each thread handles H/THREADS = 16 input floats = 4 x float4,
// and emits 8 output floats = 4 x float2.

__global__ __launch_bounds__(THREADS, 8)
void quant_pack_kernel(const float* __restrict__ x,
                       float* __restrict__ out_packed,
                       float* __restrict__ out_scales)
{
    const int row = blockIdx.x;
    const float4* __restrict__ xrow =
        reinterpret_cast<const float4*>(x + (size_t)row * H);

    // Load 4 float4 per thread, stride THREADS for coalescing; keep in regs.
    float4 v[4];
    float m = 0.0f;
#pragma unroll
    for (int c = 0; c < 4; ++c) {
        v[c] = xrow[c * THREADS + threadIdx.x];
        m = fmaxf(m, fmaxf(fmaxf(fabsf(v[c].x), fabsf(v[c].y)),
                           fmaxf(fabsf(v[c].z), fabsf(v[c].w))));
    }

    // Block absmax reduction: warp shuffle + shared across 8 warps.
#pragma unroll
    for (int o = 16; o > 0; o >>= 1)
        m = fmaxf(m, __shfl_xor_sync(0xffffffffu, m, o));

    __shared__ float warpmax[THREADS / 32];
    __shared__ float s_inv;
    const int wid = threadIdx.x >> 5;
    if ((threadIdx.x & 31) == 0) warpmax[wid] = m;
    __syncthreads();
    if (threadIdx.x == 0) {
        float mm = warpmax[0];
#pragma unroll
        for (int i = 1; i < THREADS / 32; ++i) mm = fmaxf(mm, warpmax[i]);
        const float sc = mm / 7.0f;     // exact divide, once per row
        out_scales[row] = sc;
        s_inv = 1.0f / sc;              // exact reciprocal, once per row
    }
    __syncthreads();
    const float inv = s_inv;

    // Quantize from registers; each float4 -> 2 packed signed bytes -> float2.
    float2* __restrict__ orow =
        reinterpret_cast<float2*>(out_packed + (size_t)row * HP);
#pragma unroll
    for (int c = 0; c < 4; ++c) {
        int q0 = min(max(__float2int_rn(v[c].x * inv), -8), 7);
        int q1 = min(max(__float2int_rn(v[c].y * inv), -8), 7);
        int q2 = min(max(__float2int_rn(v[c].z * inv), -8), 7);
        int q3 = min(max(__float2int_rn(v[c].w * inv), -8), 7);
        // byte0 = (q1<<4)|(q0&0xF), byte1 = (q3<<4)|(q2&0xF), as SIGNED int8,
        // then emitted as float (harness concat upcasts int8 -> float32).
        const int8_t b0 = (int8_t)(((q1 & 0xF) << 4) | (q0 & 0xF));
        const int8_t b1 = (int8_t)(((q3 & 0xF) << 4) | (q2 & 0xF));
        float2 o;
        o.x = (float)b0;
        o.y = (float)b1;
        orow[c * THREADS + threadIdx.x] = o;
    }
}

extern "C" void kernel_launch(void* const* d_in, const int* in_sizes, int n_in,
                              void* d_out, int out_size)
{
    const float* x = (const float*)d_in[0];
    const int n_elems = in_sizes[0];
    const int N = n_elems / H;                       // 8192 rows

    float* out_packed = (float*)d_out;
    float* out_scales = (float*)d_out + (size_t)N * HP;

    quant_pack_kernel<<<N, THREADS>>>(x, out_packed, out_scales);
}

// round 6
// speedup vs baseline: 1.0049x; 1.0049x over previous
#include <cuda_runtime.h>
#include <cstdint>

// Quantizer: per-row symmetric int4 quant + nibble pack. x: [8192, 4096] fp32.
// Output = concat(packed, scales) upcast to fp32:
//   out[0 .. N*2048)       fp32 value of each packed signed byte
//   out[N*2048 .. +N)      fp32 per-row scale (absmax / 7)
//
// (Resubmission: Round-5 bench was an infra failure — container never ran it.)
// R5 changes vs 33.0us baseline: paired input mapping -> float4 (STG.128)
// output stores; __ldcs/__stcs streaming hints; warp-shuffle final reduce.

#define H 4096
#define HP (H / 2)
#define THREADS 256
// thread t owns input float4s {2t, 2t+1, 512+2t, 512+2t+1} (16 floats),
// emitting output float4s {t, 256+t} (8 packed-byte floats).

__device__ __forceinline__ float pack2(float a, float b, float inv) {
    int q0 = min(max(__float2int_rn(a * inv), -8), 7);
    int q1 = min(max(__float2int_rn(b * inv), -8), 7);
    return (float)((int8_t)(((q1 & 0xF) << 4) | (q0 & 0xF)));
}

__global__ __launch_bounds__(THREADS, 8)
void quant_pack_kernel(const float* __restrict__ x,
                       float* __restrict__ out_packed,
                       float* __restrict__ out_scales)
{
    const int t = threadIdx.x;
    const int row = blockIdx.x;
    const float4* __restrict__ xrow =
        reinterpret_cast<const float4*>(x + (size_t)row * H);

    // Streaming loads; keep all 16 floats in registers.
    float4 v0 = __ldcs(&xrow[2 * t]);
    float4 v1 = __ldcs(&xrow[2 * t + 1]);
    float4 v2 = __ldcs(&xrow[512 + 2 * t]);
    float4 v3 = __ldcs(&xrow[512 + 2 * t + 1]);

    float m = fmaxf(fmaxf(fabsf(v0.x), fabsf(v0.y)), fmaxf(fabsf(v0.z), fabsf(v0.w)));
    m = fmaxf(m, fmaxf(fmaxf(fabsf(v1.x), fabsf(v1.y)), fmaxf(fabsf(v1.z), fabsf(v1.w))));
    m = fmaxf(m, fmaxf(fmaxf(fabsf(v2.x), fabsf(v2.y)), fmaxf(fabsf(v2.z), fabsf(v2.w))));
    m = fmaxf(m, fmaxf(fmaxf(fabsf(v3.x), fabsf(v3.y)), fmaxf(fabsf(v3.z), fabsf(v3.w))));

    // Warp absmax, then cross-warp via shared + warp-0 shuffle reduce.
#pragma unroll
    for (int o = 16; o > 0; o >>= 1)
        m = fmaxf(m, __shfl_xor_sync(0xffffffffu, m, o));

    __shared__ float warpmax[THREADS / 32];
    __shared__ float s_inv;
    if ((t & 31) == 0) warpmax[t >> 5] = m;
    __syncthreads();
    if (t < 32) {
        float mm = (t < THREADS / 32) ? warpmax[t] : 0.0f;
#pragma unroll
        for (int o = 4; o > 0; o >>= 1)
            mm = fmaxf(mm, __shfl_xor_sync(0xffffffffu, mm, o));
        if (t == 0) {
            const float sc = mm / 7.0f;   // exact divide, once per row
            out_scales[row] = sc;
            s_inv = 1.0f / sc;            // exact reciprocal, once per row
        }
    }
    __syncthreads();
    const float inv = s_inv;

    // Two float4 (STG.128) streaming stores per thread.
    float4* __restrict__ orow =
        reinterpret_cast<float4*>(out_packed + (size_t)row * HP);
    float4 o0, o1;
    o0.x = pack2(v0.x, v0.y, inv);
    o0.y = pack2(v0.z, v0.w, inv);
    o0.z = pack2(v1.x, v1.y, inv);
    o0.w = pack2(v1.z, v1.w, inv);
    o1.x = pack2(v2.x, v2.y, inv);
    o1.y = pack2(v2.z, v2.w, inv);
    o1.z = pack2(v3.x, v3.y, inv);
    o1.w = pack2(v3.z, v3.w, inv);
    __stcs(&orow[t], o0);
    __stcs(&orow[256 + t], o1);
}

extern "C" void kernel_launch(void* const* d_in, const int* in_sizes, int n_in,
                              void* d_out, int out_size)
{
    const float* x = (const float*)d_in[0];
    const int N = in_sizes[0] / H;                   // 8192 rows

    float* out_packed = (float*)d_out;
    float* out_scales = (float*)d_out + (size_t)N * HP;

    quant_pack_kernel<<<N, THREADS>>>(x, out_packed, out_scales);
}